// round 11
// baseline (speedup 1.0000x reference)
#include <cuda_runtime.h>
#include <cuda_bf16.h>

#define N_ATOMS   5000
#define N_EDGES   200000
#define N_TRIPLES 4000000
#define D_NODE    128
#define D_EDGE    128
#define N_BASIS   9

// Scratch (no allocations allowed)
__device__ float g_atoms[N_ATOMS * N_BASIS];       // sigmoid(node@W_atom+b) [5000 x 9]
__device__ float g_edge_atoms[N_EDGES * N_BASIS];  // atoms[graph_dst[e]]    [200000 x 9]
__device__ float g_new_bonds[N_EDGES * N_BASIS];   // segment sums           [200000 x 9]
__device__ int   g_seg_start[N_EDGES + 1];         // run boundaries in sorted seg_ids

// ---------------------------------------------------------------------------
// Kernel 1: atoms = sigmoid(node_feat @ W_atom + b_atom)   fp32
// ---------------------------------------------------------------------------
__global__ void atoms_kernel(const float* __restrict__ node_feat,
                             const float* __restrict__ W_atom,
                             const float* __restrict__ b_atom) {
    int id = blockIdx.x * blockDim.x + threadIdx.x;
    if (id >= N_ATOMS * N_BASIS) return;
    int a = id / N_BASIS;
    int j = id % N_BASIS;
    float acc = b_atom[j];
    const float* nf = node_feat + a * D_NODE;
    #pragma unroll 8
    for (int k = 0; k < D_NODE; k++)
        acc = fmaf(nf[k], W_atom[k * N_BASIS + j], acc);
    g_atoms[id] = 1.0f / (1.0f + __expf(-acc));
}

// ---------------------------------------------------------------------------
// Kernel 1b: seg_start[e] = lower_bound(seg_ids, e)  (seg_ids is sorted)
// ---------------------------------------------------------------------------
__global__ void seg_start_kernel(const int* __restrict__ seg_ids) {
    int e = blockIdx.x * blockDim.x + threadIdx.x;
    if (e > N_EDGES) return;
    if (e == N_EDGES) { g_seg_start[N_EDGES] = N_TRIPLES; return; }
    int lo = 0, hi = N_TRIPLES;
    while (lo < hi) {
        int mid = (lo + hi) >> 1;
        if (__ldg(seg_ids + mid) < e) lo = mid + 1; else hi = mid;
    }
    g_seg_start[e] = lo;
}

// ---------------------------------------------------------------------------
// Kernel 1c: edge_atoms[e][j] = atoms[graph_dst[e]][j]   (7.2 MB, L2-resident)
// Fuses the graph_dst hop out of the hot loop. ~3 us.
// ---------------------------------------------------------------------------
__global__ void edge_atoms_kernel(const int* __restrict__ graph_dst) {
    int id = blockIdx.x * blockDim.x + threadIdx.x;
    if (id >= N_EDGES * N_BASIS) return;
    int e2 = id / N_BASIS;
    int j  = id - e2 * N_BASIS;
    g_edge_atoms[id] = g_atoms[__ldg(graph_dst + e2) * N_BASIS + j];
}

// ---------------------------------------------------------------------------
// Kernel 2 (v9): warp-per-edge, batched prefetch, L2-resident edge_atoms.
//
// No shared memory at all (no table preamble, no syncs). 27 active lanes:
// group g = lane/9 -> triple s+3k+g, column j = lane%9. Batch of 8 steps:
// 8 independent tb LDGs + 8 lg LDGs (L1-hit: 96 consecutive bytes) + 8
// edge_atoms gathers (L2-resident 7.2 MB, one hop). Per-batch issue work is
// ~2/3 of the previous version (no LDS, no CVT, no gd hop). fp32 end to end.
// Epilogue: 2 shuffles + coalesced 9-float plain store. Zero atomics.
// ---------------------------------------------------------------------------
#define TPB_T    512
#define GRID_T   592                          // 4 blocks/SM x 148
#define NWARPS_T (GRID_T * (TPB_T / 32))      // 9472
#define UB 8

__global__ __launch_bounds__(TPB_T, 4) void triples_kernel(
    const float* __restrict__ three_basis,
    const int*   __restrict__ lg_dst) {

    const int lane   = threadIdx.x & 31;
    const int group  = lane / 9;               // 0,1,2 (3 for lanes 27..31)
    const int j      = lane - group * 9;       // basis column
    const bool active = (lane < 27);
    const int warp_global = blockIdx.x * (TPB_T / 32) + (threadIdx.x >> 5);

    for (int e = warp_global; e < N_EDGES; e += NWARPS_T) {
        const int s   = __ldg(g_seg_start + e);
        const int len = __ldg(g_seg_start + e + 1) - s;

        const float* tbp = three_basis + (size_t)s * 9 + lane;  // +27/step
        const int*   lgp = lg_dst + s + group;                  // +3/step

        float acc = 0.f;
        for (int k0 = 0; k0 < len; k0 += 3 * UB) {
            float v[UB];
            int   lgv[UB];

            // independent streaming loads (tb: DRAM stream, lg: L1-hit runs)
            #pragma unroll
            for (int u = 0; u < UB; u++) {
                const int k = k0 + 3 * u;
                const bool p = active && (k + group) < len;
                v[u]   = p ? __ldg(tbp + 9 * k) : 0.f;
                lgv[u] = p ? __ldg(lgp + k)     : 0;
            }
            // one-hop gathers from L2-resident edge_atoms (v=0 masks inactive)
            #pragma unroll
            for (int u = 0; u < UB; u++) {
                float a = __ldg(g_edge_atoms + (size_t)lgv[u] * N_BASIS + j);
                acc = fmaf(v[u], a, acc);
            }
        }

        // reduce 3 groups onto lanes 0..8
        float a1 = __shfl_down_sync(0xFFFFFFFFu, acc, 9);
        float a2 = __shfl_down_sync(0xFFFFFFFFu, acc, 18);
        if (lane < N_BASIS)
            g_new_bonds[(size_t)e * N_BASIS + lane] = acc + a1 + a2;
    }
}

// ---------------------------------------------------------------------------
// Kernel 3: out = edge_feat + silu(g)*sigmoid(s)
// E_TILE=100, ONE tile per block (grid 2000 = N_EDGES/100): better preamble
// amortization, ~13.5 blocks/SM resident -> ~85% occ, one less sync.
// ---------------------------------------------------------------------------
#define E_TILE   100
#define NB_TILE  (E_TILE * N_BASIS)            // 900 floats
#define MLP_GRID (N_EDGES / E_TILE)            // 2000

__global__ __launch_bounds__(D_EDGE) void mlp_kernel(
    const float* __restrict__ edge_feat,
    const float* __restrict__ W_gate, const float* __restrict__ b_gate,
    const float* __restrict__ W_sig,  const float* __restrict__ b_sig,
    float* __restrict__ out) {

    __shared__ float s_nb[NB_TILE];

    const int j  = threadIdx.x;
    const int e0 = blockIdx.x * E_TILE;

    // stage nb tile (coalesced 900 consecutive floats)
    const float* nb_src = g_new_bonds + (size_t)e0 * N_BASIS;
    #pragma unroll
    for (int i = j; i < NB_TILE; i += D_EDGE)
        s_nb[i] = nb_src[i];

    // per-thread column weights (overlaps with staging)
    float wg[N_BASIS], ws[N_BASIS];
    #pragma unroll
    for (int k = 0; k < N_BASIS; k++) {
        wg[k] = W_gate[k * D_EDGE + j];
        ws[k] = W_sig [k * D_EDGE + j];
    }
    const float bg = b_gate[j];
    const float bs = b_sig[j];

    __syncthreads();

    #pragma unroll 2
    for (int e = 0; e < E_TILE; e += 2) {
        const float* nb0 = s_nb + e * N_BASIS;
        const float* nb1 = nb0 + N_BASIS;

        size_t idx0 = (size_t)(e0 + e) * D_EDGE + j;
        size_t idx1 = idx0 + D_EDGE;
        float ef0 = edge_feat[idx0];
        float ef1 = edge_feat[idx1];

        float g0 = bg, s0 = bs, g1 = bg, s1 = bs;
        #pragma unroll
        for (int k = 0; k < N_BASIS; k++) {
            float n0 = nb0[k], n1 = nb1[k];
            g0 = fmaf(n0, wg[k], g0);
            s0 = fmaf(n0, ws[k], s0);
            g1 = fmaf(n1, wg[k], g1);
            s1 = fmaf(n1, ws[k], s1);
        }
        // up = g / ((1+e^-g)(1+e^-s)) == silu(g)*sigmoid(s)
        float d0 = (1.f + __expf(-g0)) * (1.f + __expf(-s0));
        float d1 = (1.f + __expf(-g1)) * (1.f + __expf(-s1));
        out[idx0] = ef0 + __fdividef(g0, d0);
        out[idx1] = ef1 + __fdividef(g1, d1);
    }
}

// ---------------------------------------------------------------------------
// Launch
// ---------------------------------------------------------------------------
extern "C" void kernel_launch(void* const* d_in, const int* in_sizes, int n_in,
                              void* d_out, int out_size) {
    const float* node_feat   = (const float*)d_in[0];
    const float* edge_feat   = (const float*)d_in[1];
    const float* three_basis = (const float*)d_in[2];
    const float* W_atom      = (const float*)d_in[4];
    const float* b_atom      = (const float*)d_in[5];
    const float* W_gate      = (const float*)d_in[6];
    const float* b_gate      = (const float*)d_in[7];
    const float* W_sig       = (const float*)d_in[8];
    const float* b_sig       = (const float*)d_in[9];
    const int*   graph_dst   = (const int*)d_in[10];
    const int*   lg_dst      = (const int*)d_in[12];
    const int*   seg_ids     = (const int*)d_in[13];
    float*       out         = (float*)d_out;

    atoms_kernel<<<(N_ATOMS * N_BASIS + 255) / 256, 256>>>(node_feat, W_atom, b_atom);
    seg_start_kernel<<<(N_EDGES + 1 + 255) / 256, 256>>>(seg_ids);
    edge_atoms_kernel<<<(N_EDGES * N_BASIS + 255) / 256, 256>>>(graph_dst);
    triples_kernel<<<GRID_T, TPB_T>>>(three_basis, lg_dst);
    mlp_kernel<<<MLP_GRID, D_EDGE>>>(edge_feat, W_gate, b_gate, W_sig, b_sig, out);
}

// round 12
// speedup vs baseline: 1.1189x; 1.1189x over previous
#include <cuda_runtime.h>
#include <cuda_bf16.h>

#define N_ATOMS   5000
#define N_EDGES   200000
#define N_TRIPLES 4000000
#define D_NODE    128
#define D_EDGE    128
#define N_BASIS   9

// Scratch (no allocations allowed)
__device__ float g_atoms[N_ATOMS * N_BASIS];       // sigmoid(node@W_atom+b) [5000 x 9]
__device__ float g_edge_atoms[N_EDGES * N_BASIS];  // atoms[graph_dst[e]]    [200000 x 9]
__device__ float g_new_bonds[N_EDGES * N_BASIS];   // segment sums           [200000 x 9]
__device__ int   g_seg_start[N_EDGES + 1];         // run boundaries in sorted seg_ids

// ---------------------------------------------------------------------------
// Kernel 1: atoms = sigmoid(node_feat @ W_atom + b_atom)   fp32
// ---------------------------------------------------------------------------
__global__ void atoms_kernel(const float* __restrict__ node_feat,
                             const float* __restrict__ W_atom,
                             const float* __restrict__ b_atom) {
    int id = blockIdx.x * blockDim.x + threadIdx.x;
    if (id >= N_ATOMS * N_BASIS) return;
    int a = id / N_BASIS;
    int j = id % N_BASIS;
    float acc = b_atom[j];
    const float* nf = node_feat + a * D_NODE;
    #pragma unroll 8
    for (int k = 0; k < D_NODE; k++)
        acc = fmaf(nf[k], W_atom[k * N_BASIS + j], acc);
    g_atoms[id] = 1.0f / (1.0f + __expf(-acc));
}

// ---------------------------------------------------------------------------
// Kernel 1b: seg_start[e] = lower_bound(seg_ids, e)  (seg_ids is sorted)
// ---------------------------------------------------------------------------
__global__ void seg_start_kernel(const int* __restrict__ seg_ids) {
    int e = blockIdx.x * blockDim.x + threadIdx.x;
    if (e > N_EDGES) return;
    if (e == N_EDGES) { g_seg_start[N_EDGES] = N_TRIPLES; return; }
    int lo = 0, hi = N_TRIPLES;
    while (lo < hi) {
        int mid = (lo + hi) >> 1;
        if (__ldg(seg_ids + mid) < e) lo = mid + 1; else hi = mid;
    }
    g_seg_start[e] = lo;
}

// ---------------------------------------------------------------------------
// Kernel 1c: edge_atoms[e][j] = atoms[graph_dst[e]][j]   (7.2 MB, L2-resident)
// ---------------------------------------------------------------------------
__global__ void edge_atoms_kernel(const int* __restrict__ graph_dst) {
    int id = blockIdx.x * blockDim.x + threadIdx.x;
    if (id >= N_EDGES * N_BASIS) return;
    int e2 = id / N_BASIS;
    int j  = id - e2 * N_BASIS;
    g_edge_atoms[id] = g_atoms[__ldg(graph_dst + e2) * N_BASIS + j];
}

// ---------------------------------------------------------------------------
// Kernel 2 (v9, measured 59.0 us): warp-per-edge, batched prefetch,
// L2-resident edge_atoms, no smem, fp32 end to end. Zero atomics.
// ---------------------------------------------------------------------------
#define TPB_T    512
#define GRID_T   592                          // 4 blocks/SM x 148
#define NWARPS_T (GRID_T * (TPB_T / 32))      // 9472
#define UB 8

__global__ __launch_bounds__(TPB_T, 4) void triples_kernel(
    const float* __restrict__ three_basis,
    const int*   __restrict__ lg_dst) {

    const int lane   = threadIdx.x & 31;
    const int group  = lane / 9;               // 0,1,2 (3 for lanes 27..31)
    const int j      = lane - group * 9;       // basis column
    const bool active = (lane < 27);
    const int warp_global = blockIdx.x * (TPB_T / 32) + (threadIdx.x >> 5);

    for (int e = warp_global; e < N_EDGES; e += NWARPS_T) {
        const int s   = __ldg(g_seg_start + e);
        const int len = __ldg(g_seg_start + e + 1) - s;

        const float* tbp = three_basis + (size_t)s * 9 + lane;  // +27/step
        const int*   lgp = lg_dst + s + group;                  // +3/step

        float acc = 0.f;
        for (int k0 = 0; k0 < len; k0 += 3 * UB) {
            float v[UB];
            int   lgv[UB];

            #pragma unroll
            for (int u = 0; u < UB; u++) {
                const int k = k0 + 3 * u;
                const bool p = active && (k + group) < len;
                v[u]   = p ? __ldg(tbp + 9 * k) : 0.f;
                lgv[u] = p ? __ldg(lgp + k)     : 0;
            }
            #pragma unroll
            for (int u = 0; u < UB; u++) {
                float a = __ldg(g_edge_atoms + (size_t)lgv[u] * N_BASIS + j);
                acc = fmaf(v[u], a, acc);
            }
        }

        float a1 = __shfl_down_sync(0xFFFFFFFFu, acc, 9);
        float a2 = __shfl_down_sync(0xFFFFFFFFu, acc, 18);
        if (lane < N_BASIS)
            g_new_bonds[(size_t)e * N_BASIS + lane] = acc + a1 + a2;
    }
}

// ---------------------------------------------------------------------------
// Kernel 3 (EXACT R10 version, measured 50.4 us): persistent grid-stride,
// E_TILE=64, grid 2368 (16 blocks/SM).
// ---------------------------------------------------------------------------
#define E_TILE   64
#define NB_TILE  (E_TILE * N_BASIS)            // 576 floats
#define N_TILES  (N_EDGES / E_TILE)            // 3125
#define MLP_GRID 2368                          // 16 blocks/SM * 148

__global__ __launch_bounds__(D_EDGE) void mlp_kernel(
    const float* __restrict__ edge_feat,
    const float* __restrict__ W_gate, const float* __restrict__ b_gate,
    const float* __restrict__ W_sig,  const float* __restrict__ b_sig,
    float* __restrict__ out) {

    __shared__ float s_nb[NB_TILE];

    const int j = threadIdx.x;

    float wg[N_BASIS], ws[N_BASIS];
    #pragma unroll
    for (int k = 0; k < N_BASIS; k++) {
        wg[k] = W_gate[k * D_EDGE + j];
        ws[k] = W_sig [k * D_EDGE + j];
    }
    const float bg = b_gate[j];
    const float bs = b_sig[j];

    for (int tile = blockIdx.x; tile < N_TILES; tile += MLP_GRID) {
        const int e0 = tile * E_TILE;

        __syncthreads();
        const float* nb_src = g_new_bonds + (size_t)e0 * N_BASIS;
        #pragma unroll
        for (int i = j; i < NB_TILE; i += D_EDGE)
            s_nb[i] = nb_src[i];
        __syncthreads();

        #pragma unroll 2
        for (int e = 0; e < E_TILE; e += 2) {
            const float* nb0 = s_nb + e * N_BASIS;
            const float* nb1 = nb0 + N_BASIS;

            size_t idx0 = (size_t)(e0 + e) * D_EDGE + j;
            size_t idx1 = idx0 + D_EDGE;
            float ef0 = edge_feat[idx0];
            float ef1 = edge_feat[idx1];

            float g0 = bg, s0 = bs, g1 = bg, s1 = bs;
            #pragma unroll
            for (int k = 0; k < N_BASIS; k++) {
                float n0 = nb0[k], n1 = nb1[k];
                g0 = fmaf(n0, wg[k], g0);
                s0 = fmaf(n0, ws[k], s0);
                g1 = fmaf(n1, wg[k], g1);
                s1 = fmaf(n1, ws[k], s1);
            }
            // up = g / ((1+e^-g)(1+e^-s)) == silu(g)*sigmoid(s)
            float d0 = (1.f + __expf(-g0)) * (1.f + __expf(-s0));
            float d1 = (1.f + __expf(-g1)) * (1.f + __expf(-s1));
            out[idx0] = ef0 + __fdividef(g0, d0);
            out[idx1] = ef1 + __fdividef(g1, d1);
        }
    }
}

// ---------------------------------------------------------------------------
// Launch
// ---------------------------------------------------------------------------
extern "C" void kernel_launch(void* const* d_in, const int* in_sizes, int n_in,
                              void* d_out, int out_size) {
    const float* node_feat   = (const float*)d_in[0];
    const float* edge_feat   = (const float*)d_in[1];
    const float* three_basis = (const float*)d_in[2];
    const float* W_atom      = (const float*)d_in[4];
    const float* b_atom      = (const float*)d_in[5];
    const float* W_gate      = (const float*)d_in[6];
    const float* b_gate      = (const float*)d_in[7];
    const float* W_sig       = (const float*)d_in[8];
    const float* b_sig       = (const float*)d_in[9];
    const int*   graph_dst   = (const int*)d_in[10];
    const int*   lg_dst      = (const int*)d_in[12];
    const int*   seg_ids     = (const int*)d_in[13];
    float*       out         = (float*)d_out;

    atoms_kernel<<<(N_ATOMS * N_BASIS + 255) / 256, 256>>>(node_feat, W_atom, b_atom);
    seg_start_kernel<<<(N_EDGES + 1 + 255) / 256, 256>>>(seg_ids);
    edge_atoms_kernel<<<(N_EDGES * N_BASIS + 255) / 256, 256>>>(graph_dst);
    triples_kernel<<<GRID_T, TPB_T>>>(three_basis, lg_dst);
    mlp_kernel<<<MLP_GRID, D_EDGE>>>(edge_feat, W_gate, b_gate, W_sig, b_sig, out);
}

// round 13
// speedup vs baseline: 1.1652x; 1.0414x over previous
#include <cuda_runtime.h>
#include <cuda_bf16.h>
#include <cstdint>

#define N_ATOMS   5000
#define N_EDGES   200000
#define N_TRIPLES 4000000
#define D_NODE    128
#define D_EDGE    128
#define N_BASIS   9

// Scratch (no allocations allowed)
__device__ float g_atoms[N_ATOMS * N_BASIS];       // sigmoid(node@W_atom+b) [5000 x 9]
__device__ float g_edge_atoms[N_EDGES * N_BASIS];  // atoms[graph_dst[e]]    [200000 x 9]
__device__ float g_new_bonds[N_EDGES * N_BASIS];   // segment sums           [200000 x 9]
__device__ int   g_seg_start[N_EDGES + 1];         // run boundaries in sorted seg_ids

// packed f32x2 helpers (Blackwell FFMA2 is only reachable via PTX)
#define FMA2(d, a, b, c) \
    asm("fma.rn.f32x2 %0, %1, %2, %3;" : "=l"(d) : "l"(a), "l"(b), "l"(c))
#define PACK2(out, lo, hi) \
    asm("mov.b64 %0, {%1, %2};" : "=l"(out) : "f"(lo), "f"(hi))
#define UNPACK2(lo, hi, in) \
    asm("mov.b64 {%0, %1}, %2;" : "=f"(lo), "=f"(hi) : "l"(in))

// ---------------------------------------------------------------------------
// Kernel 1: atoms = sigmoid(node_feat @ W_atom + b_atom)   fp32
// ---------------------------------------------------------------------------
__global__ void atoms_kernel(const float* __restrict__ node_feat,
                             const float* __restrict__ W_atom,
                             const float* __restrict__ b_atom) {
    int id = blockIdx.x * blockDim.x + threadIdx.x;
    if (id >= N_ATOMS * N_BASIS) return;
    int a = id / N_BASIS;
    int j = id % N_BASIS;
    float acc = b_atom[j];
    const float* nf = node_feat + a * D_NODE;
    #pragma unroll 8
    for (int k = 0; k < D_NODE; k++)
        acc = fmaf(nf[k], W_atom[k * N_BASIS + j], acc);
    g_atoms[id] = 1.0f / (1.0f + __expf(-acc));
}

// ---------------------------------------------------------------------------
// Kernel 1b: seg_start[e] = lower_bound(seg_ids, e)  (seg_ids is sorted)
// ---------------------------------------------------------------------------
__global__ void seg_start_kernel(const int* __restrict__ seg_ids) {
    int e = blockIdx.x * blockDim.x + threadIdx.x;
    if (e > N_EDGES) return;
    if (e == N_EDGES) { g_seg_start[N_EDGES] = N_TRIPLES; return; }
    int lo = 0, hi = N_TRIPLES;
    while (lo < hi) {
        int mid = (lo + hi) >> 1;
        if (__ldg(seg_ids + mid) < e) lo = mid + 1; else hi = mid;
    }
    g_seg_start[e] = lo;
}

// ---------------------------------------------------------------------------
// Kernel 1c: edge_atoms[e][j] = atoms[graph_dst[e]][j]   (7.2 MB, L2-resident)
// ---------------------------------------------------------------------------
__global__ void edge_atoms_kernel(const int* __restrict__ graph_dst) {
    int id = blockIdx.x * blockDim.x + threadIdx.x;
    if (id >= N_EDGES * N_BASIS) return;
    int e2 = id / N_BASIS;
    int j  = id - e2 * N_BASIS;
    g_edge_atoms[id] = g_atoms[__ldg(graph_dst + e2) * N_BASIS + j];
}

// ---------------------------------------------------------------------------
// Kernel 2 (v10): warp-per-edge, UNPREDICATED full batches + predicated tail.
//
// Inactive lanes (27..31) get base pointers clamped to offset 0 so every
// load in the unpredicated main loop is in-bounds for all lanes; their acc
// is garbage but the shuffle reduction only consumes lanes 0..26.
// Main-loop step: LDG(tb,imm) + LDG(lg,imm) + IMAD + LDG(ea,L2) + FFMA.
// ---------------------------------------------------------------------------
#define TPB_T    512
#define GRID_T   592                          // 4 blocks/SM x 148
#define NWARPS_T (GRID_T * (TPB_T / 32))      // 9472
#define UB 8

__global__ __launch_bounds__(TPB_T, 4) void triples_kernel(
    const float* __restrict__ three_basis,
    const int*   __restrict__ lg_dst) {

    const int lane   = threadIdx.x & 31;
    const int group  = lane / 9;               // 0,1,2 (3 for lanes 27..31)
    const int j      = lane - group * 9;       // basis column
    const bool active = (lane < 27);
    const int warp_global = blockIdx.x * (TPB_T / 32) + (threadIdx.x >> 5);

    for (int e = warp_global; e < N_EDGES; e += NWARPS_T) {
        const int s   = __ldg(g_seg_start + e);
        const int len = __ldg(g_seg_start + e + 1) - s;

        // clamp inactive lanes to offset 0: all main-loop loads in-bounds
        const float* tbp = three_basis + (active ? (size_t)s * 9 + lane : 0);
        const int*   lgp = lg_dst + (active ? s + group : 0);

        float acc = 0.f;
        const int nfull = len / (3 * UB);
        int k0 = 0;
        for (int b = 0; b < nfull; b++, k0 += 3 * UB) {
            float v[UB];
            int   lgv[UB];
            #pragma unroll
            for (int u = 0; u < UB; u++) {             // no predication
                v[u]   = __ldg(tbp + 9 * k0 + 27 * u);
                lgv[u] = __ldg(lgp + k0 + 3 * u);
            }
            #pragma unroll
            for (int u = 0; u < UB; u++)
                acc = fmaf(v[u],
                           __ldg(g_edge_atoms + (size_t)lgv[u] * N_BASIS + j),
                           acc);
        }
        if (k0 < len) {                                // predicated tail batch
            #pragma unroll
            for (int u = 0; u < UB; u++) {
                const int k = k0 + 3 * u;
                const bool p = active && (k + group) < len;
                float v   = p ? __ldg(tbp + 9 * k) : 0.f;
                int   lgv = p ? __ldg(lgp + k)     : 0;
                acc = fmaf(v,
                           __ldg(g_edge_atoms + (size_t)lgv * N_BASIS + j),
                           acc);
            }
        }

        float a1 = __shfl_down_sync(0xFFFFFFFFu, acc, 9);
        float a2 = __shfl_down_sync(0xFFFFFFFFu, acc, 18);
        if (lane < N_BASIS)
            g_new_bonds[(size_t)e * N_BASIS + lane] = acc + a1 + a2;
    }
}

// ---------------------------------------------------------------------------
// Kernel 3 (v3): persistent grid-stride + PACKED f32x2 FMA.
// nb tile staged TRANSPOSED [9][E_TILE] so an edge-pair's nb[k] is one
// aligned LDS.64 broadcast; weights pre-packed (w,w) in u64 registers;
// (g0,g1)/(s0,s1) accumulate via fma.rn.f32x2 -> FMA instr count halved.
// ---------------------------------------------------------------------------
#define E_TILE   64
#define NB_TILE  (E_TILE * N_BASIS)            // 576 floats
#define N_TILES  (N_EDGES / E_TILE)            // 3125
#define MLP_GRID 2368                          // 16 blocks/SM * 148

__global__ __launch_bounds__(D_EDGE) void mlp_kernel(
    const float* __restrict__ edge_feat,
    const float* __restrict__ W_gate, const float* __restrict__ b_gate,
    const float* __restrict__ W_sig,  const float* __restrict__ b_sig,
    float* __restrict__ out) {

    __shared__ float s_nb[NB_TILE];            // transposed [9][E_TILE]

    const int j = threadIdx.x;

    // packed per-column weights/biases: (w,w) in u64, built once per block
    uint64_t wg2[N_BASIS], ws2[N_BASIS], bg2, bs2;
    #pragma unroll
    for (int k = 0; k < N_BASIS; k++) {
        float wgk = W_gate[k * D_EDGE + j];
        float wsk = W_sig [k * D_EDGE + j];
        PACK2(wg2[k], wgk, wgk);
        PACK2(ws2[k], wsk, wsk);
    }
    {
        float bgv = b_gate[j], bsv = b_sig[j];
        PACK2(bg2, bgv, bgv);
        PACK2(bs2, bsv, bsv);
    }

    for (int tile = blockIdx.x; tile < N_TILES; tile += MLP_GRID) {
        const int e0 = tile * E_TILE;

        __syncthreads();
        const float* nb_src = g_new_bonds + (size_t)e0 * N_BASIS;
        #pragma unroll
        for (int i = j; i < NB_TILE; i += D_EDGE) {
            int ee = i / N_BASIS, kk = i - ee * N_BASIS;
            s_nb[kk * E_TILE + ee] = nb_src[i];    // transpose on store
        }
        __syncthreads();

        #pragma unroll 2
        for (int e = 0; e < E_TILE; e += 2) {
            size_t idx0 = (size_t)(e0 + e) * D_EDGE + j;
            size_t idx1 = idx0 + D_EDGE;
            float ef0 = edge_feat[idx0];
            float ef1 = edge_feat[idx1];

            uint64_t accg = bg2, accs = bs2;
            #pragma unroll
            for (int k = 0; k < N_BASIS; k++) {
                uint64_t n2 = *reinterpret_cast<const uint64_t*>(
                                  &s_nb[k * E_TILE + e]);   // LDS.64 broadcast
                FMA2(accg, n2, wg2[k], accg);
                FMA2(accs, n2, ws2[k], accs);
            }
            float g0, g1, s0, s1;
            UNPACK2(g0, g1, accg);
            UNPACK2(s0, s1, accs);

            // up = g / ((1+e^-g)(1+e^-s)) == silu(g)*sigmoid(s)
            float d0 = (1.f + __expf(-g0)) * (1.f + __expf(-s0));
            float d1 = (1.f + __expf(-g1)) * (1.f + __expf(-s1));
            out[idx0] = ef0 + __fdividef(g0, d0);
            out[idx1] = ef1 + __fdividef(g1, d1);
        }
    }
}

// ---------------------------------------------------------------------------
// Launch
// ---------------------------------------------------------------------------
extern "C" void kernel_launch(void* const* d_in, const int* in_sizes, int n_in,
                              void* d_out, int out_size) {
    const float* node_feat   = (const float*)d_in[0];
    const float* edge_feat   = (const float*)d_in[1];
    const float* three_basis = (const float*)d_in[2];
    const float* W_atom      = (const float*)d_in[4];
    const float* b_atom      = (const float*)d_in[5];
    const float* W_gate      = (const float*)d_in[6];
    const float* b_gate      = (const float*)d_in[7];
    const float* W_sig       = (const float*)d_in[8];
    const float* b_sig       = (const float*)d_in[9];
    const int*   graph_dst   = (const int*)d_in[10];
    const int*   lg_dst      = (const int*)d_in[12];
    const int*   seg_ids     = (const int*)d_in[13];
    float*       out         = (float*)d_out;

    atoms_kernel<<<(N_ATOMS * N_BASIS + 255) / 256, 256>>>(node_feat, W_atom, b_atom);
    seg_start_kernel<<<(N_EDGES + 1 + 255) / 256, 256>>>(seg_ids);
    edge_atoms_kernel<<<(N_EDGES * N_BASIS + 255) / 256, 256>>>(graph_dst);
    triples_kernel<<<GRID_T, TPB_T>>>(three_basis, lg_dst);
    mlp_kernel<<<MLP_GRID, D_EDGE>>>(edge_feat, W_gate, b_gate, W_sig, b_sig, out);
}

// round 14
// speedup vs baseline: 1.2767x; 1.0957x over previous
#include <cuda_runtime.h>
#include <cuda_bf16.h>
#include <cstdint>

#define N_ATOMS   5000
#define N_EDGES   200000
#define N_TRIPLES 4000000
#define D_NODE    128
#define D_EDGE    128
#define N_BASIS   9

// Scratch (no allocations allowed)
__device__ float g_atoms[N_ATOMS * N_BASIS];       // sigmoid(node@W_atom+b) [5000 x 9]
__device__ float g_edge_atoms[N_EDGES * N_BASIS];  // atoms[graph_dst[e]]    [200000 x 9]
__device__ float g_new_bonds[N_EDGES * N_BASIS];   // segment sums           [200000 x 9]
__device__ int   g_seg_start[N_EDGES + 1];         // run boundaries in sorted seg_ids

// packed f32x2 helpers (Blackwell FFMA2 is only reachable via PTX)
#define FMA2(d, a, b, c) \
    asm("fma.rn.f32x2 %0, %1, %2, %3;" : "=l"(d) : "l"(a), "l"(b), "l"(c))
#define PACK2(out, lo, hi) \
    asm("mov.b64 %0, {%1, %2};" : "=l"(out) : "f"(lo), "f"(hi))
#define UNPACK2(lo, hi, in) \
    asm("mov.b64 {%0, %1}, %2;" : "=f"(lo), "=f"(hi) : "l"(in))

// ---------------------------------------------------------------------------
// Kernel 1 (FUSED): blocks [0, ATOM_BLOCKS) compute the atoms table;
// blocks [ATOM_BLOCKS, ..) compute seg_start via binary search.
// Independent work -> one launch, overlapping compute-bound and latency-bound.
// ---------------------------------------------------------------------------
#define PREP_TPB     256
#define ATOM_BLOCKS  ((N_ATOMS * N_BASIS + PREP_TPB - 1) / PREP_TPB)      // 176
#define SEG_BLOCKS   ((N_EDGES + 1 + PREP_TPB - 1) / PREP_TPB)            // 782
#define PREP_GRID    (ATOM_BLOCKS + SEG_BLOCKS)

__global__ void prep_kernel(const float* __restrict__ node_feat,
                            const float* __restrict__ W_atom,
                            const float* __restrict__ b_atom,
                            const int*   __restrict__ seg_ids) {
    if (blockIdx.x < ATOM_BLOCKS) {
        int id = blockIdx.x * PREP_TPB + threadIdx.x;
        if (id >= N_ATOMS * N_BASIS) return;
        int a = id / N_BASIS;
        int j = id % N_BASIS;
        float acc = b_atom[j];
        const float* nf = node_feat + a * D_NODE;
        #pragma unroll 8
        for (int k = 0; k < D_NODE; k++)
            acc = fmaf(nf[k], W_atom[k * N_BASIS + j], acc);
        g_atoms[id] = 1.0f / (1.0f + __expf(-acc));
    } else {
        int e = (blockIdx.x - ATOM_BLOCKS) * PREP_TPB + threadIdx.x;
        if (e > N_EDGES) return;
        if (e == N_EDGES) { g_seg_start[N_EDGES] = N_TRIPLES; return; }
        int lo = 0, hi = N_TRIPLES;
        while (lo < hi) {
            int mid = (lo + hi) >> 1;
            if (__ldg(seg_ids + mid) < e) lo = mid + 1; else hi = mid;
        }
        g_seg_start[e] = lo;
    }
}

// ---------------------------------------------------------------------------
// Kernel 1c: edge_atoms[e][j] = atoms[graph_dst[e]][j]   (7.2 MB, L2-resident)
// ---------------------------------------------------------------------------
__global__ void edge_atoms_kernel(const int* __restrict__ graph_dst) {
    int id = blockIdx.x * blockDim.x + threadIdx.x;
    if (id >= N_EDGES * N_BASIS) return;
    int e2 = id / N_BASIS;
    int j  = id - e2 * N_BASIS;
    g_edge_atoms[id] = g_atoms[__ldg(graph_dst + e2) * N_BASIS + j];
}

// ---------------------------------------------------------------------------
// Kernel 2 (v11): warp-per-edge with TIERED batches matched to len~Poisson(20):
//   tier 1: unpredicated batches of 12 triples (4 steps, MLP=8)
//   tier 2: unpredicated single steps (3 triples)
//   tier 3: one final predicated step (<=2 triples)
// ~95 issue slots per typical edge vs ~192 previously (predication gone from
// >90% of work). Inactive lanes 27..31 use clamped base pointers so all
// unpredicated loads stay in-bounds; their acc is never consumed.
// ---------------------------------------------------------------------------
#define TPB_T    512
#define GRID_T   592                          // 4 blocks/SM x 148
#define NWARPS_T (GRID_T * (TPB_T / 32))      // 9472
#define UB4 4

__global__ __launch_bounds__(TPB_T, 4) void triples_kernel(
    const float* __restrict__ three_basis,
    const int*   __restrict__ lg_dst) {

    const int lane   = threadIdx.x & 31;
    const int group  = lane / 9;               // 0,1,2 (3 for lanes 27..31)
    const int j      = lane - group * 9;       // basis column
    const bool active = (lane < 27);
    const int warp_global = blockIdx.x * (TPB_T / 32) + (threadIdx.x >> 5);

    // per-thread pre-offset ea base: gather addr = eab + 36*lg
    const char* eab = (const char*)g_edge_atoms + 4 * j;

    for (int e = warp_global; e < N_EDGES; e += NWARPS_T) {
        const int s   = __ldg(g_seg_start + e);
        const int len = __ldg(g_seg_start + e + 1) - s;

        // clamp inactive lanes to offset 0: all unpredicated loads in-bounds
        const float* tbp = three_basis + (active ? (size_t)s * 9 + lane : 0);
        const int*   lgp = lg_dst + (active ? s + group : 0);

        float acc = 0.f;
        int k0 = 0;

        // tier 1: unpredicated batches of 4 steps (12 triples)
        for (; k0 + 12 <= len; k0 += 12) {
            float v[UB4];
            int   lgv[UB4];
            #pragma unroll
            for (int u = 0; u < UB4; u++) {
                v[u]   = __ldg(tbp + 9 * (k0 + 3 * u));
                lgv[u] = __ldg(lgp + k0 + 3 * u);
            }
            #pragma unroll
            for (int u = 0; u < UB4; u++)
                acc = fmaf(v[u],
                           __ldg((const float*)(eab + 36 * (size_t)lgv[u])),
                           acc);
        }
        // tier 2: unpredicated single steps (3 triples)
        for (; k0 + 3 <= len; k0 += 3) {
            float v  = __ldg(tbp + 9 * k0);
            int  lgv = __ldg(lgp + k0);
            acc = fmaf(v, __ldg((const float*)(eab + 36 * (size_t)lgv)), acc);
        }
        // tier 3: final partial step (len - k0 in {1,2})
        if (k0 < len) {
            const bool p = active && (k0 + group) < len;
            float v  = p ? __ldg(tbp + 9 * k0) : 0.f;
            int  lgv = p ? __ldg(lgp + k0)     : 0;
            acc = fmaf(v, __ldg((const float*)(eab + 36 * (size_t)lgv)), acc);
        }

        float a1 = __shfl_down_sync(0xFFFFFFFFu, acc, 9);
        float a2 = __shfl_down_sync(0xFFFFFFFFu, acc, 18);
        if (lane < N_BASIS)
            g_new_bonds[(size_t)e * N_BASIS + lane] = acc + a1 + a2;
    }
}

// ---------------------------------------------------------------------------
// Kernel 3 (unchanged, measured-good): persistent grid-stride + f32x2 FMA.
// ---------------------------------------------------------------------------
#define E_TILE   64
#define NB_TILE  (E_TILE * N_BASIS)            // 576 floats
#define N_TILES  (N_EDGES / E_TILE)            // 3125
#define MLP_GRID 2368                          // 16 blocks/SM * 148

__global__ __launch_bounds__(D_EDGE) void mlp_kernel(
    const float* __restrict__ edge_feat,
    const float* __restrict__ W_gate, const float* __restrict__ b_gate,
    const float* __restrict__ W_sig,  const float* __restrict__ b_sig,
    float* __restrict__ out) {

    __shared__ float s_nb[NB_TILE];            // transposed [9][E_TILE]

    const int j = threadIdx.x;

    uint64_t wg2[N_BASIS], ws2[N_BASIS], bg2, bs2;
    #pragma unroll
    for (int k = 0; k < N_BASIS; k++) {
        float wgk = W_gate[k * D_EDGE + j];
        float wsk = W_sig [k * D_EDGE + j];
        PACK2(wg2[k], wgk, wgk);
        PACK2(ws2[k], wsk, wsk);
    }
    {
        float bgv = b_gate[j], bsv = b_sig[j];
        PACK2(bg2, bgv, bgv);
        PACK2(bs2, bsv, bsv);
    }

    for (int tile = blockIdx.x; tile < N_TILES; tile += MLP_GRID) {
        const int e0 = tile * E_TILE;

        __syncthreads();
        const float* nb_src = g_new_bonds + (size_t)e0 * N_BASIS;
        #pragma unroll
        for (int i = j; i < NB_TILE; i += D_EDGE) {
            int ee = i / N_BASIS, kk = i - ee * N_BASIS;
            s_nb[kk * E_TILE + ee] = nb_src[i];    // transpose on store
        }
        __syncthreads();

        #pragma unroll 2
        for (int e = 0; e < E_TILE; e += 2) {
            size_t idx0 = (size_t)(e0 + e) * D_EDGE + j;
            size_t idx1 = idx0 + D_EDGE;
            float ef0 = edge_feat[idx0];
            float ef1 = edge_feat[idx1];

            uint64_t accg = bg2, accs = bs2;
            #pragma unroll
            for (int k = 0; k < N_BASIS; k++) {
                uint64_t n2 = *reinterpret_cast<const uint64_t*>(
                                  &s_nb[k * E_TILE + e]);   // LDS.64 broadcast
                FMA2(accg, n2, wg2[k], accg);
                FMA2(accs, n2, ws2[k], accs);
            }
            float g0, g1, s0, s1;
            UNPACK2(g0, g1, accg);
            UNPACK2(s0, s1, accs);

            // up = g / ((1+e^-g)(1+e^-s)) == silu(g)*sigmoid(s)
            float d0 = (1.f + __expf(-g0)) * (1.f + __expf(-s0));
            float d1 = (1.f + __expf(-g1)) * (1.f + __expf(-s1));
            out[idx0] = ef0 + __fdividef(g0, d0);
            out[idx1] = ef1 + __fdividef(g1, d1);
        }
    }
}

// ---------------------------------------------------------------------------
// Launch (4 kernels)
// ---------------------------------------------------------------------------
extern "C" void kernel_launch(void* const* d_in, const int* in_sizes, int n_in,
                              void* d_out, int out_size) {
    const float* node_feat   = (const float*)d_in[0];
    const float* edge_feat   = (const float*)d_in[1];
    const float* three_basis = (const float*)d_in[2];
    const float* W_atom      = (const float*)d_in[4];
    const float* b_atom      = (const float*)d_in[5];
    const float* W_gate      = (const float*)d_in[6];
    const float* b_gate      = (const float*)d_in[7];
    const float* W_sig       = (const float*)d_in[8];
    const float* b_sig       = (const float*)d_in[9];
    const int*   graph_dst   = (const int*)d_in[10];
    const int*   lg_dst      = (const int*)d_in[12];
    const int*   seg_ids     = (const int*)d_in[13];
    float*       out         = (float*)d_out;

    prep_kernel<<<PREP_GRID, PREP_TPB>>>(node_feat, W_atom, b_atom, seg_ids);
    edge_atoms_kernel<<<(N_EDGES * N_BASIS + 255) / 256, 256>>>(graph_dst);
    triples_kernel<<<GRID_T, TPB_T>>>(three_basis, lg_dst);
    mlp_kernel<<<MLP_GRID, D_EDGE>>>(edge_feat, W_gate, b_gate, W_sig, b_sig, out);
}